// round 11
// baseline (speedup 1.0000x reference)
#include <cuda_runtime.h>
#include <stdint.h>
#include <math.h>

#define BB  4
#define TT  256
#define TS  512
#define HH  1024
#define VV  32100
#define NROW (BB*TT)
#define N4  (VV/4)          // 8025 float4 per row
#define ROWBYTES (VV*4)     // 128400 B

#define HSLOTS 2048
#define HMASK  (HSLOTS-1)
#define PGRID  148

// 8 segments: segs 0-6 = 1024 float4 (16384 B), seg 7 = 857 float4 (13712 B)
#define SEGB    16384
#define SEG7B   (ROWBYTES - 7*SEGB)   // 13712

#define OFF_ROW   0
#define OFF_HKEY  128512
#define OFF_HVAL  (OFF_HKEY + HSLOTS*4)
#define OFF_RED   (OFF_HVAL + HSLOTS*4)
#define OFF_MBAR  (OFF_RED + 96*4)
#define SMEM_TOT  (OFF_MBAR + 8*8 + 16)

__device__ float g_encproj[BB * TS];
__device__ float g_decproj[BB * TT];
__device__ unsigned g_arrive = 0;     // monotone across graph replays

__device__ __forceinline__ uint32_t smem_u32(const void* p) {
    uint32_t a;
    asm("{ .reg .u64 t; cvta.to.shared.u64 t, %1; cvt.u32.u64 %0, t; }"
        : "=r"(a) : "l"(p));
    return a;
}
__device__ __forceinline__ void mbar_init(uint32_t mbar, uint32_t cnt) {
    asm volatile("mbarrier.init.shared.b64 [%0], %1;" :: "r"(mbar), "r"(cnt) : "memory");
}
__device__ __forceinline__ void mbar_expect_tx(uint32_t mbar, uint32_t bytes) {
    asm volatile("mbarrier.arrive.expect_tx.shared.b64 _, [%0], %1;"
                 :: "r"(mbar), "r"(bytes) : "memory");
}
__device__ __forceinline__ void mbar_wait(uint32_t mbar, uint32_t phase) {
    asm volatile(
        "{\n\t.reg .pred P;\n\t"
        "W_%=:\n\t"
        "mbarrier.try_wait.parity.acquire.cta.shared::cta.b64 P, [%0], %1, 0x989680;\n\t"
        "@P bra D_%=;\n\t"
        "bra W_%=;\n\t"
        "D_%=:\n\t}"
        :: "r"(mbar), "r"(phase) : "memory");
}
__device__ __forceinline__ void tma_1d_g2s(uint32_t dst, const void* src,
                                           uint32_t bytes, uint32_t mbar) {
    asm volatile(
        "cp.async.bulk.shared::cta.global.mbarrier::complete_tx::bytes [%0], [%1], %2, [%3];"
        :: "r"(dst), "l"(src), "r"(bytes), "r"(mbar) : "memory");
}

__device__ __forceinline__ float4 xform(float4 x, float c, float pinvS, bool fastp) {
    float4 r;
    if (fastp) {
        r.x = x.x + c; r.y = x.y + c; r.z = x.z + c; r.w = x.w + c;
    } else {
        r.x = __logf(fmaf(pinvS, __expf(x.x), 1e-12f));
        r.y = __logf(fmaf(pinvS, __expf(x.y), 1e-12f));
        r.z = __logf(fmaf(pinvS, __expf(x.z), 1e-12f));
        r.w = __logf(fmaf(pinvS, __expf(x.w), 1e-12f));
    }
    return r;
}

// ---------------------------------------------------------------------------
// Single persistent kernel.
// Prologue: balanced in-kernel proj (task = warp*PGRID + blockIdx.x so every
// CTA does ~21 one-warp dots), split grid-barrier: ARRIVE right after proj,
// then row-0 loads + full pass A (proj-independent), THEN wait. Main loop =
// round-9 merged store/wait/refill pipeline with per-chunk mbarriers.
// ---------------------------------------------------------------------------
__global__ __launch_bounds__(1024, 1)
void pgen_fused_kernel(const float* __restrict__ dec,
                       const float* __restrict__ attn,
                       const float* __restrict__ enc,
                       const float* __restrict__ logits,
                       const float* __restrict__ Wg,
                       const float* __restrict__ bg,
                       const int*   __restrict__ sids,
                       float*       __restrict__ out)
{
    extern __shared__ __align__(128) char smem[];
    float4* rowbuf = (float4*)(smem + OFF_ROW);
    int*    hkey   = (int*)  (smem + OFF_HKEY);
    float*  hval   = (float*)(smem + OFF_HVAL);
    float*  red    = (float*)(smem + OFF_RED);
    const uint32_t mbar0  = smem_u32(smem + OFF_MBAR);
    const uint32_t rowdst = smem_u32(smem + OFF_ROW);

    const int t    = threadIdx.x;
    const int warp = t >> 5;
    const int lane = t & 31;
    const bool tail = (t + 7 * 1024) < N4;

    hkey[t] = -1;          hval[t] = 0.f;
    hkey[t + 1024] = -1;   hval[t + 1024] = 0.f;
    if (t == 0) {
        #pragma unroll
        for (int j = 0; j < 8; ++j) mbar_init(mbar0 + j * 8, 1);
    }
    __syncthreads();

    int row = blockIdx.x;

    // kick all 8 segment TMAs for row+G right away
    if (t == 0 && row + PGRID < NROW) {
        const float* src = logits + (size_t)(row + PGRID) * VV;
        #pragma unroll
        for (int j = 0; j < 8; ++j) {
            const uint32_t bytes = (j < 7) ? SEGB : SEG7B;
            mbar_expect_tx(mbar0 + j * 8, bytes);
            tma_1d_g2s(rowdst + j * SEGB, src + j * 4096, bytes, mbar0 + j * 8);
        }
    }

    // ---- in-kernel proj, BALANCED striping: task = warp*PGRID + blockIdx.x ----
    {
        const int gw   = warp * PGRID + blockIdx.x;   // every CTA: ~21 tasks
        const int nEnc = BB * TS;                     // 2048
        const int nDec = BB * TT;                     // 1024
        if (gw < nEnc) {
            const float4* rp = (const float4*)(enc + (size_t)gw * HH);
            const float4* w  = (const float4*)(Wg);
            float s = 0.f;
            #pragma unroll
            for (int i = 0; i < HH / 128; ++i) {
                float4 a4 = rp[lane + i * 32];
                float4 b4 = w[lane + i * 32];
                s += a4.x * b4.x + a4.y * b4.y + a4.z * b4.z + a4.w * b4.w;
            }
            #pragma unroll
            for (int o = 16; o > 0; o >>= 1) s += __shfl_xor_sync(0xffffffffu, s, o);
            if (lane == 0) g_encproj[gw] = s;
        } else if (gw < nEnc + nDec) {
            const int r = gw - nEnc;
            const float4* rp = (const float4*)(dec + (size_t)r * HH);
            const float4* w  = (const float4*)(Wg + HH);
            float s = 0.f;
            #pragma unroll
            for (int i = 0; i < HH / 128; ++i) {
                float4 a4 = rp[lane + i * 32];
                float4 b4 = w[lane + i * 32];
                s += a4.x * b4.x + a4.y * b4.y + a4.z * b4.z + a4.w * b4.w;
            }
            #pragma unroll
            for (int o = 16; o > 0; o >>= 1) s += __shfl_xor_sync(0xffffffffu, s, o);
            if (lane == 0) g_decproj[r] = s + bg[0];
        }
    }
    __threadfence();     // release proj writes (gpu scope)
    __syncthreads();     // whole CTA's proj done

    // ---- ARRIVE now; do proj-independent work before the WAIT ----
    unsigned bar_target = 0;
    if (t == 0) {
        unsigned ticket = atomicAdd(&g_arrive, 1u);
        bar_target = (ticket / PGRID + 1u) * PGRID;
    }

    // row0 register loads (overlap barrier skew)
    float4 v[8];
    {
        const float4* lrow = (const float4*)(logits + (size_t)row * VV);
        #pragma unroll
        for (int i = 0; i < 7; ++i) v[i] = lrow[t + i * 1024];
        if (tail) v[7] = lrow[t + 7 * 1024];
    }

    // pass A for row0 (needs no proj results) — hides the rest of the skew
    float se = 0.f, xmn = 1e30f;
    #pragma unroll
    for (int i = 0; i < 7; ++i) {
        se += __expf(v[i].x) + __expf(v[i].y) + __expf(v[i].z) + __expf(v[i].w);
        xmn = fminf(xmn, fminf(fminf(v[i].x, v[i].y), fminf(v[i].z, v[i].w)));
    }
    if (tail) {
        se += __expf(v[7].x) + __expf(v[7].y) + __expf(v[7].z) + __expf(v[7].w);
        xmn = fminf(xmn, fminf(fminf(v[7].x, v[7].y), fminf(v[7].z, v[7].w)));
    }

    // prefetch attn/sids for row0 (proj-independent)
    float a0 = 0.f;
    int   id0 = 0;
    if (t < TS) {
        a0  = attn[(size_t)row * TS + t];
        id0 = sids[(row / TT) * TS + t];
    }

    // ---- WAIT: all CTAs' proj visible ----
    if (t == 0) {
        while (*(volatile unsigned*)&g_arrive < bar_target) __nanosleep(64);
        __threadfence();   // acquire
    }
    __syncthreads();

    // ---- scatter row0 (uses encproj) ----
    float pg = 0.f;
    if (t < TS) {
        pg = a0 * g_encproj[(row / TT) * TS + t];
        int slot = (int)(((unsigned)id0 * 2654435761u) >> 17) & HMASK;
        for (;;) {
            int prev = atomicCAS(&hkey[slot], -1, id0);
            if (prev == -1 || prev == id0) { atomicAdd(&hval[slot], a0); break; }
            slot = (slot + 1) & HMASK;
        }
    }
    float dp = g_decproj[row];

    // prefetch scatter inputs + decproj for row+G
    float a_in = 0.f, ep_in = 0.f, dp_nxt = 0.f;
    int   id_in = 0;
    if (row + PGRID < NROW) {
        const int bn = (row + PGRID) / TT;
        if (t < TS) {
            a_in  = attn[(size_t)(row + PGRID) * TS + t];
            id_in = sids[bn * TS + t];
            ep_in = g_encproj[bn * TS + t];
        }
        dp_nxt = g_decproj[row + PGRID];
    }

    uint32_t phase = 0;

    while (true) {
        // ---- reduction of (pg, se, xmn) ----
        float rpg = pg, rse = se, rmn = xmn;
        #pragma unroll
        for (int o = 16; o > 0; o >>= 1) {
            rpg += __shfl_xor_sync(0xffffffffu, rpg, o);
            rse += __shfl_xor_sync(0xffffffffu, rse, o);
            rmn  = fminf(rmn, __shfl_xor_sync(0xffffffffu, rmn, o));
        }
        if (lane == 0) { red[warp] = rpg; red[32 + warp] = rse; red[64 + warp] = rmn; }
        __syncthreads();
        if (warp == 0) {
            float a2 = red[lane];
            float s2 = red[32 + lane];
            float m2 = red[64 + lane];
            #pragma unroll
            for (int o = 16; o > 0; o >>= 1) {
                a2 += __shfl_xor_sync(0xffffffffu, a2, o);
                s2 += __shfl_xor_sync(0xffffffffu, s2, o);
                m2  = fminf(m2, __shfl_xor_sync(0xffffffffu, m2, o));
            }
            if (lane == 0) { red[0] = a2; red[32] = s2; red[64] = m2; }
        }
        __syncthreads();

        const float z     = red[0] + dp;
        const float p     = 1.f / (1.f + __expf(-z));
        const float q     = 1.f - p;
        const float pinvS = p / red[32];
        const float c     = __logf(pinvS);
        const bool  fastp = (pinvS * __expf(red[64])) >= 1e-9f;

        // prefetch fixup gathers (hash complete; land under merged loop)
        const float* lsc = logits + (size_t)row * VV;
        const int vid0 = hkey[t];
        const int vid1 = hkey[t + 1024];
        float xf0 = 0.f, xf1 = 0.f, m0 = 0.f, m1 = 0.f;
        if (vid0 >= 0) { xf0 = lsc[vid0]; m0 = hval[t]; }
        if (vid1 >= 0) { xf1 = lsc[vid1]; m1 = hval[t + 1024]; }

        const int  next      = row + PGRID;
        const bool has_next  = next < NROW;
        const bool has_next2 = next + PGRID < NROW;

        // ---- merged loop: store chunk i -> wait seg i -> refill + exp-sum ----
        float4* orow = (float4*)(out + (size_t)row * VV);
        se = 0.f; xmn = 1e30f;
        if (has_next) {
            #pragma unroll
            for (int i = 0; i < 8; ++i) {
                const bool live = (i < 7) || tail;
                if (live) orow[t + i * 1024] = xform(v[i], c, pinvS, fastp);
                mbar_wait(mbar0 + i * 8, phase);
                if (live) {
                    v[i] = rowbuf[t + i * 1024];
                    se += __expf(v[i].x) + __expf(v[i].y) + __expf(v[i].z) + __expf(v[i].w);
                    xmn = fminf(xmn, fminf(fminf(v[i].x, v[i].y), fminf(v[i].z, v[i].w)));
                }
            }
            phase ^= 1;
        } else {
            #pragma unroll
            for (int i = 0; i < 7; ++i)
                orow[t + i * 1024] = xform(v[i], c, pinvS, fastp);
            if (tail)
                orow[t + 7 * 1024] = xform(v[7], c, pinvS, fastp);
        }

        // single sync: stores ordered before fixup, rowbuf fully consumed
        __syncthreads();

        // single kick point: all 8 segment TMAs for row r+2G
        if (t == 0 && has_next && has_next2) {
            const float* src2 = logits + (size_t)(next + PGRID) * VV;
            #pragma unroll
            for (int j = 0; j < 8; ++j) {
                const uint32_t bytes = (j < 7) ? SEGB : SEG7B;
                mbar_expect_tx(mbar0 + j * 8, bytes);
                tma_1d_g2s(rowdst + j * SEGB, src2 + j * 4096, bytes, mbar0 + j * 8);
            }
        }

        // fixup (gathers in registers) + hash clear
        float* osc = out + (size_t)row * VV;
        if (vid0 >= 0) {
            osc[vid0] = __logf(fmaf(pinvS, __expf(xf0), fmaf(q, m0, 1e-12f)));
            hkey[t] = -1;  hval[t] = 0.f;
        }
        if (vid1 >= 0) {
            osc[vid1] = __logf(fmaf(pinvS, __expf(xf1), fmaf(q, m1, 1e-12f)));
            hkey[t + 1024] = -1;  hval[t + 1024] = 0.f;
        }

        if (!has_next) break;

        __syncthreads();   // hash clean before next scatter

        // scatter row r+G (inputs prefetched)
        pg = 0.f;
        if (t < TS) {
            pg = a_in * ep_in;
            int slot = (int)(((unsigned)id_in * 2654435761u) >> 17) & HMASK;
            for (;;) {
                int prev = atomicCAS(&hkey[slot], -1, id_in);
                if (prev == -1 || prev == id_in) { atomicAdd(&hval[slot], a_in); break; }
                slot = (slot + 1) & HMASK;
            }
        }
        dp = dp_nxt;

        // prefetch scatter inputs for row r+2G
        if (has_next2) {
            const int bn = (next + PGRID) / TT;
            if (t < TS) {
                a_in  = attn[(size_t)(next + PGRID) * TS + t];
                id_in = sids[bn * TS + t];
                ep_in = g_encproj[bn * TS + t];
            }
            dp_nxt = g_decproj[next + PGRID];
        }

        row = next;
    }
}

extern "C" void kernel_launch(void* const* d_in, const int* in_sizes, int n_in,
                              void* d_out, int out_size)
{
    const float* dec    = (const float*)d_in[0];
    const float* attn   = (const float*)d_in[1];
    const float* enc    = (const float*)d_in[2];
    const float* logits = (const float*)d_in[3];
    const float* Wg     = (const float*)d_in[4];
    const float* bg     = (const float*)d_in[5];
    const int*   sids   = (const int*)  d_in[6];
    float*       out    = (float*)d_out;

    cudaFuncSetAttribute(pgen_fused_kernel,
                         cudaFuncAttributeMaxDynamicSharedMemorySize, SMEM_TOT);

    pgen_fused_kernel<<<PGRID, 1024, SMEM_TOT>>>(dec, attn, enc, logits,
                                                 Wg, bg, sids, out);
}

// round 12
// speedup vs baseline: 1.0055x; 1.0055x over previous
#include <cuda_runtime.h>
#include <stdint.h>
#include <math.h>

#define BB  4
#define TT  256
#define TS  512
#define HH  1024
#define VV  32100
#define NROW (BB*TT)
#define N4  8025            // float4 per row
#define ROWBYTES (VV*4)

#define HSLOTS 2048
#define HMASK  (HSLOTS-1)

#define SEGF4   1024        // float4 per full segment (16 KB)
#define SEGB    16384
#define LASTF4  857         // seg 7: 8025 - 7*1024
#define LASTB   13712
#define NSEG    8           // segments per pass
#define RING    3

// smem layout (bytes)
#define OFF_RING  0
#define OFF_HKEY  (RING*SEGB)                 // 49152
#define OFF_HVAL  (OFF_HKEY + HSLOTS*4)
#define OFF_RED   (OFF_HVAL + HSLOTS*4)
#define OFF_MBAR  (OFF_RED + 64*4)
#define SMEM_TOT  (OFF_MBAR + RING*8 + 16)    // ~65.9 KB -> 3 CTAs/SM

__device__ float g_encproj[BB * TS];
__device__ float g_decproj[BB * TT];

__device__ __forceinline__ uint32_t smem_u32(const void* p) {
    uint32_t a;
    asm("{ .reg .u64 t; cvta.to.shared.u64 t, %1; cvt.u32.u64 %0, t; }"
        : "=r"(a) : "l"(p));
    return a;
}
__device__ __forceinline__ void mbar_init(uint32_t mbar, uint32_t cnt) {
    asm volatile("mbarrier.init.shared.b64 [%0], %1;" :: "r"(mbar), "r"(cnt) : "memory");
}
__device__ __forceinline__ void mbar_expect_tx(uint32_t mbar, uint32_t bytes) {
    asm volatile("mbarrier.arrive.expect_tx.shared.b64 _, [%0], %1;"
                 :: "r"(mbar), "r"(bytes) : "memory");
}
__device__ __forceinline__ void mbar_wait(uint32_t mbar, uint32_t phase) {
    asm volatile(
        "{\n\t.reg .pred P;\n\t"
        "W_%=:\n\t"
        "mbarrier.try_wait.parity.acquire.cta.shared::cta.b64 P, [%0], %1, 0x989680;\n\t"
        "@P bra D_%=;\n\t"
        "bra W_%=;\n\t"
        "D_%=:\n\t}"
        :: "r"(mbar), "r"(phase) : "memory");
}
__device__ __forceinline__ void tma_1d_g2s(uint32_t dst, const void* src,
                                           uint32_t bytes, uint32_t mbar) {
    asm volatile(
        "cp.async.bulk.shared::cta.global.mbarrier::complete_tx::bytes [%0], [%1], %2, [%3];"
        :: "r"(dst), "l"(src), "r"(bytes), "r"(mbar) : "memory");
}

// ---------------------------------------------------------------------------
// Kernel 1: one warp per dot; replaces the einsum via
//   context . W_top == sum_s attn[s] * (enc[s] . W_top)
// ---------------------------------------------------------------------------
__global__ void proj_kernel(const float* __restrict__ dec,
                            const float* __restrict__ enc,
                            const float* __restrict__ Wg,
                            const float* __restrict__ bg)
{
    const int gw   = (blockIdx.x * blockDim.x + threadIdx.x) >> 5;
    const int lane = threadIdx.x & 31;
    const int nEnc = BB * TS;
    const int nDec = BB * TT;

    if (gw < nEnc) {
        const float4* row = (const float4*)(enc + (size_t)gw * HH);
        const float4* w   = (const float4*)(Wg);
        float s = 0.f;
        #pragma unroll
        for (int i = 0; i < HH / 128; ++i) {
            float4 a = row[lane + i * 32];
            float4 b = w[lane + i * 32];
            s += a.x * b.x + a.y * b.y + a.z * b.z + a.w * b.w;
        }
        #pragma unroll
        for (int o = 16; o > 0; o >>= 1) s += __shfl_xor_sync(0xffffffffu, s, o);
        if (lane == 0) g_encproj[gw] = s;
    } else if (gw < nEnc + nDec) {
        const int r = gw - nEnc;
        const float4* row = (const float4*)(dec + (size_t)r * HH);
        const float4* w   = (const float4*)(Wg + HH);
        float s = 0.f;
        #pragma unroll
        for (int i = 0; i < HH / 128; ++i) {
            float4 a = row[lane + i * 32];
            float4 b = w[lane + i * 32];
            s += a.x * b.x + a.y * b.y + a.z * b.z + a.w * b.w;
        }
        #pragma unroll
        for (int o = 16; o > 0; o >>= 1) s += __shfl_xor_sync(0xffffffffu, s, o);
        if (lane == 0) g_decproj[r] = s + bg[0];
    }
}

__device__ __forceinline__ float4 xform(float4 x, float c, float pinvS, bool fastp) {
    float4 r;
    if (fastp) {
        r.x = x.x + c; r.y = x.y + c; r.z = x.z + c; r.w = x.w + c;
    } else {
        r.x = __logf(fmaf(pinvS, __expf(x.x), 1e-12f));
        r.y = __logf(fmaf(pinvS, __expf(x.y), 1e-12f));
        r.z = __logf(fmaf(pinvS, __expf(x.z), 1e-12f));
        r.w = __logf(fmaf(pinvS, __expf(x.w), 1e-12f));
    }
    return r;
}

// ---------------------------------------------------------------------------
// Kernel 2: one CTA (512 thr) per row, 3 CTAs/SM. The row streams twice
// through a 3-slot TMA ring (16 logical segments: 0-7 = pass 1 sum,
// 8-15 = pass 2 xform+store; segment s lands in slot s%3, phase (s/3)&1).
// Serial phases of one CTA overlap the streaming of the other two CTAs on
// the same SM. Pass-2 reads are L2-resident re-reads.
// ---------------------------------------------------------------------------
__global__ __launch_bounds__(512, 3)
void pgen_main(const float* __restrict__ attn,
               const float* __restrict__ logits,
               const int*   __restrict__ sids,
               float*       __restrict__ out)
{
    extern __shared__ __align__(128) char smem[];
    float4* ring = (float4*)(smem + OFF_RING);
    int*    hkey = (int*)  (smem + OFF_HKEY);
    float*  hval = (float*)(smem + OFF_HVAL);
    float*  red  = (float*)(smem + OFF_RED);
    const uint32_t mbar0   = smem_u32(smem + OFF_MBAR);
    const uint32_t ringdst = smem_u32(smem + OFF_RING);

    const int t    = threadIdx.x;
    const int warp = t >> 5;          // 0..15
    const int lane = t & 31;
    const int row  = blockIdx.x;
    const int b    = row / TT;

    // init hash (4 slots/thread) + ring mbarriers
    #pragma unroll
    for (int i = 0; i < 4; ++i) { hkey[t + i * 512] = -1; hval[t + i * 512] = 0.f; }
    if (t == 0) {
        #pragma unroll
        for (int j = 0; j < RING; ++j) mbar_init(mbar0 + j * 8, 1);
    }
    __syncthreads();

    // kick segments 0,1,2 (all full-size)
    const float*  lrow  = logits + (size_t)row * VV;
    const float4* lrow4 = (const float4*)lrow;
    if (t == 0) {
        #pragma unroll
        for (int j = 0; j < RING; ++j) {
            mbar_expect_tx(mbar0 + j * 8, SEGB);
            tma_1d_g2s(ringdst + j * SEGB, lrow4 + j * SEGF4, SEGB, mbar0 + j * 8);
        }
    }

    // scatter + p_gen partial (TS == blockDim: every thread has one source pos)
    float pg;
    {
        const float a  = attn[(size_t)row * TS + t];
        const int   id = sids[b * TS + t];
        pg = a * g_encproj[b * TS + t];
        int slot = (int)(((unsigned)id * 2654435761u) >> 17) & HMASK;
        for (;;) {
            int prev = atomicCAS(&hkey[slot], -1, id);
            if (prev == -1 || prev == id) { atomicAdd(&hval[slot], a); break; }
            slot = (slot + 1) & HMASK;
        }
    }

    // ---- pass 1: stream segments 0..7, sum exp + min ----
    float se = 0.f, xmn = 1e30f;
    #pragma unroll
    for (int s = 0; s < NSEG; ++s) {
        const int slot = s % RING;
        const int ph   = (s / RING) & 1;
        mbar_wait(mbar0 + slot * 8, ph);
        const float4* seg = ring + slot * SEGF4;
        const int cnt = (s < 7) ? SEGF4 : LASTF4;
        if (t < cnt) {
            const float4 x = seg[t];
            se += __expf(x.x) + __expf(x.y) + __expf(x.z) + __expf(x.w);
            xmn = fminf(xmn, fminf(fminf(x.x, x.y), fminf(x.z, x.w)));
        }
        if (t + 512 < cnt) {
            const float4 x = seg[t + 512];
            se += __expf(x.x) + __expf(x.y) + __expf(x.z) + __expf(x.w);
            xmn = fminf(xmn, fminf(fminf(x.x, x.y), fminf(x.z, x.w)));
        }
        __syncthreads();   // slot fully consumed
        const int ls = s + RING;       // next logical segment into this slot
        if (t == 0 && ls < 2 * NSEG) {
            const int off = ls & 7;    // pass-2 repeats offsets 0..7
            const uint32_t bytes = (off < 7) ? SEGB : LASTB;
            mbar_expect_tx(mbar0 + slot * 8, bytes);
            tma_1d_g2s(ringdst + slot * SEGB, lrow4 + off * SEGF4,
                       bytes, mbar0 + slot * 8);
        }
    }

    // ---- block reduction of (pg, se, xmn) over 16 warps ----
    #pragma unroll
    for (int o = 16; o > 0; o >>= 1) {
        pg += __shfl_xor_sync(0xffffffffu, pg, o);
        se += __shfl_xor_sync(0xffffffffu, se, o);
        xmn = fminf(xmn, __shfl_xor_sync(0xffffffffu, xmn, o));
    }
    if (lane == 0) { red[warp] = pg; red[16 + warp] = se; red[32 + warp] = xmn; }
    __syncthreads();
    if (warp == 0 && lane < 16) {
        float a2 = red[lane];
        float s2 = red[16 + lane];
        float m2 = red[32 + lane];
        #pragma unroll
        for (int o = 8; o > 0; o >>= 1) {
            a2 += __shfl_xor_sync(0xffffu, a2, o);
            s2 += __shfl_xor_sync(0xffffu, s2, o);
            m2  = fminf(m2, __shfl_xor_sync(0xffffu, m2, o));
        }
        if (lane == 0) { red[0] = a2; red[16] = s2; red[32] = m2; }
    }
    __syncthreads();

    const float z     = red[0] + g_decproj[row];
    const float p     = 1.f / (1.f + __expf(-z));
    const float q     = 1.f - p;
    const float pinvS = p / red[16];
    const float c     = __logf(pinvS);
    const bool  fastp = (pinvS * __expf(red[32])) >= 1e-9f;

    // ---- pass 2: stream segments 8..15 (same row, L2-hot), xform + store ----
    float4* orow4 = (float4*)(out + (size_t)row * VV);
    #pragma unroll
    for (int s = NSEG; s < 2 * NSEG; ++s) {
        const int slot = s % RING;
        const int ph   = (s / RING) & 1;
        mbar_wait(mbar0 + slot * 8, ph);
        const float4* seg  = ring + slot * SEGF4;
        const int     off  = s - NSEG;
        const int     base = off * SEGF4;
        const int     cnt  = (off < 7) ? SEGF4 : LASTF4;
        if (t < cnt)       orow4[base + t]       = xform(seg[t],       c, pinvS, fastp);
        if (t + 512 < cnt) orow4[base + t + 512] = xform(seg[t + 512], c, pinvS, fastp);
        __syncthreads();   // slot consumed; also orders stores for fixup later
        const int ls = s + RING;
        if (t == 0 && ls < 2 * NSEG) {
            const int off2 = ls & 7;
            const uint32_t bytes = (off2 < 7) ? SEGB : LASTB;
            mbar_expect_tx(mbar0 + slot * 8, bytes);
            tma_1d_g2s(ringdst + slot * SEGB, lrow4 + off2 * SEGF4,
                       bytes, mbar0 + slot * 8);
        }
    }

    // ---- fixup: each thread owns 4 hash slots; overwrite copy positions ----
    float* osc = out + (size_t)row * VV;
    #pragma unroll
    for (int i = 0; i < 4; ++i) {
        const int s   = t + i * 512;
        const int vid = hkey[s];
        if (vid >= 0) {
            const float x = lrow[vid];   // L2-hot
            osc[vid] = __logf(fmaf(pinvS, __expf(x), fmaf(q, hval[s], 1e-12f)));
        }
    }
}

extern "C" void kernel_launch(void* const* d_in, const int* in_sizes, int n_in,
                              void* d_out, int out_size)
{
    const float* dec    = (const float*)d_in[0];
    const float* attn   = (const float*)d_in[1];
    const float* enc    = (const float*)d_in[2];
    const float* logits = (const float*)d_in[3];
    const float* Wg     = (const float*)d_in[4];
    const float* bg     = (const float*)d_in[5];
    const int*   sids   = (const int*)  d_in[6];
    float*       out    = (float*)d_out;

    cudaFuncSetAttribute(pgen_main,
                         cudaFuncAttributeMaxDynamicSharedMemorySize, SMEM_TOT);

    proj_kernel<<<(BB * TS + BB * TT) / 8, 256>>>(dec, enc, Wg, bg);
    pgen_main<<<NROW, 512, SMEM_TOT>>>(attn, logits, sids, out);
}